// round 7
// baseline (speedup 1.0000x reference)
#include <cuda_runtime.h>
#include <stdint.h>

#define HH 512
#define WW 512
#define HW (HH*WW)
#define NS 8            // samples
#define NIMG 16         // samples * {pred, mask}
#define KP 1024         // points per set
#define T_MST 128
#define NPT 8           // nodes per MST thread
#define UMAXV 0xFFFFFFFFu
#define SENTX 46000u    // retired-node x (scaled); cands land in [8.79e8, 2.39e9]
#define SKIPTHR 0x20000000u  // 2^29: all real keys below, all sentinel cands above
#define WPR 16          // 512/32 words per row

// ---------------- scratch (static device globals; no allocation) ----------------
__device__ unsigned g_mask[NIMG * 8192];          // binarized bitmasks (512x512 bits)
__device__ unsigned g_fbits[NIMG * 8192];         // lbp<THR flag bitmasks
__device__ float2   g_pts[NIMG][KP];              // selected points (r, c) float
__device__ unsigned g_pti[NIMG][KP];              // packed int coords (r<<16)|c
__device__ int2     g_edges[NIMG][KP - 1];        // MST edges (src, j)

// ---------------- 1) binarize -> bitmasks ---------------------------------------
__global__ void binarize_kernel(const float* __restrict__ mo, const float* __restrict__ lb) {
    int gid = blockIdx.x * blockDim.x + threadIdx.x;   // exactly NS*HW threads
    int s = gid >> 18;
    int p = gid & (HW - 1);
    unsigned bp = __ballot_sync(0xffffffffu, __ldg(mo + gid) > 0.0f);  // sigmoid>0.5 <=> x>0
    unsigned bm = __ballot_sync(0xffffffffu, __ldg(lb + gid) > 0.5f);
    if ((threadIdx.x & 31) == 0) {
        int w = p >> 5;
        g_mask[(2 * s)     * 8192 + w] = bp;
        g_mask[(2 * s + 1) * 8192 + w] = bm;
    }
}

// ---------------- 2) uniform LBP on bitmasks (exact) ----------------------------
__device__ __forceinline__ unsigned maj3(unsigned a, unsigned b, unsigned c) {
    return (a & b) | (c & (a ^ b));
}
__device__ __forceinline__ void sum8(const unsigned b[8],
                                     unsigned& s0, unsigned& s1, unsigned& s2, unsigned& s3) {
    unsigned t0 = b[0] ^ b[1], c0 = b[0] & b[1];
    unsigned t1 = b[2] ^ b[3], c1 = b[2] & b[3];
    unsigned t2 = b[4] ^ b[5], c2 = b[4] & b[5];
    unsigned t3 = b[6] ^ b[7], c3 = b[6] & b[7];
    unsigned u0 = t0 ^ t1, d0 = t0 & t1;
    unsigned u1 = t2 ^ t3, d1 = t2 & t3;
    s0 = u0 ^ u1;
    unsigned e0 = u0 & u1;
    unsigned p0 = c0 ^ c1 ^ c2, q0 = maj3(c0, c1, c2);
    unsigned p1 = c3 ^ d0 ^ d1, q1 = maj3(c3, d0, d1);
    s1 = p0 ^ p1 ^ e0;
    unsigned q2 = maj3(p0, p1, e0);
    s2 = q0 ^ q1 ^ q2;
    s3 = maj3(q0, q1, q2);
}

struct RowBits { unsigned C, Lc, Rc, QL, QR; };

__device__ __forceinline__ RowBits rowbits(const unsigned* __restrict__ M, int y, int w) {
    RowBits rb;
    unsigned c = __ldg(M + y * WPR + w);
    unsigned prev = (w > 0)   ? __ldg(M + y * WPR + w - 1) : 0u;
    unsigned next = (w < 15)  ? __ldg(M + y * WPR + w + 1) : 0u;
    unsigned Lc = (w > 0)  ? __funnelshift_l(prev, c, 1) : ((c << 1) | (c & 1u));
    unsigned Rc = (w < 15) ? __funnelshift_r(c, next, 1) : ((c >> 1) | (c & 0x80000000u));
    unsigned QL = Lc & c;
    if (w == 0) QL = (QL & ~1u) | (c & Rc & 1u);   // col0: quad cols {0,1}
    rb.C = c; rb.Lc = Lc; rb.Rc = Rc; rb.QL = QL; rb.QR = c & Rc;
    return rb;
}

__global__ void lbp_bits_kernel() {
    int gid = blockIdx.x * blockDim.x + threadIdx.x;   // NIMG*8192 threads
    int img = gid >> 13;
    int rem = gid & 8191;
    int r = rem >> 4;
    int w = rem & 15;
    const unsigned* __restrict__ M = g_mask + img * 8192;

    int rm = max(r - 1, 0);
    int rp = min(r + 1, HH - 1);
    RowBits Rr  = rowbits(M, r,  w);
    RowBits Rrp = rowbits(M, rp, w);
    RowBits Rpm0, Rpm1;         // row pair for dr = -0.707: {clamp(r-1), clamp(r-1)+1}
    if (r == 0) { Rpm0 = Rr; Rpm1 = Rrp; }
    else        { Rpm0 = rowbits(M, rm, w); Rpm1 = Rr; }
    unsigned Crm = (r == 0) ? Rr.C : Rpm0.C;   // C(clamp(r-1))

    unsigned b[8];
    b[0] = Rr.Rc;                 // (0, +1)
    b[2] = Crm;                   // (-1, 0)
    b[4] = Rr.Lc;                 // (0, -1)
    b[6] = Rrp.C;                 // (+1, 0)
    b[1] = Rpm0.QR & Rpm1.QR;     // (-.707, +.707)
    b[3] = Rpm0.QL & Rpm1.QL;     // (-.707, -.707)
    b[5] = Rr.QL & Rrp.QL;        // (+.707, -.707)
    b[7] = Rr.QR & Rrp.QR;        // (+.707, +.707)

    unsigned s0, s1, s2, s3;
    sum8(b, s0, s1, s2, s3);
    unsigned ok_s = ~(s3 | (s2 & (s1 | s0)));     // sum < 5

    unsigned ch[8];
#pragma unroll
    for (int k = 0; k < 8; k++) ch[k] = b[k] ^ b[(k + 7) & 7];
    unsigned c0, c1, c2, c3;
    sum8(ch, c0, c1, c2, c3);
    unsigned ok_ch = ~(c2 | c3);                  // changes <= 2 (changes is even)

    g_fbits[gid] = Rr.C & ok_s & ok_ch;           // center must be 1
}

// ---------------- 3) ordered compaction from flag bitmask ------------------------
__global__ void __launch_bounds__(1024) select_kernel() {
    const int img = blockIdx.x;
    __shared__ int s_wtot[32];
    __shared__ int s_woff[32];
    const int tid = threadIdx.x, lane = tid & 31, wrp = tid >> 5;

    g_pts[img][tid] = make_float2(0.0f, 0.0f);    // zero-pad
    g_pti[img][tid] = 0u;

    const unsigned* __restrict__ F = g_fbits + img * 8192;
    unsigned wv[8];
    int cnt = 0;
    const int w0 = tid * 8;
#pragma unroll
    for (int i = 0; i < 8; i++) { wv[i] = __ldg(F + w0 + i); cnt += __popc(wv[i]); }

    // block-wide exclusive prefix
    int incl = cnt;
#pragma unroll
    for (int d = 1; d < 32; d <<= 1) {
        int n = __shfl_up_sync(0xffffffffu, incl, d);
        if (lane >= d) incl += n;
    }
    if (lane == 31) s_wtot[wrp] = incl;
    __syncthreads();
    if (wrp == 0) {
        int t = s_wtot[lane];
        int ti = t;
#pragma unroll
        for (int d = 1; d < 32; d <<= 1) {
            int n = __shfl_up_sync(0xffffffffu, ti, d);
            if (lane >= d) ti += n;
        }
        s_woff[lane] = ti - t;
    }
    __syncthreads();
    int rank = s_woff[wrp] + (incl - cnt);

    if (rank < KP && cnt > 0) {
#pragma unroll
        for (int i = 0; i < 8; i++) {
            unsigned m = wv[i];
            int pbase = (w0 + i) << 5;
            while (m && rank < KP) {
                int b = __ffs(m) - 1;
                m &= m - 1;
                int pp = pbase + b;
                int rr = pp >> 9, cc = pp & 511;
                g_pts[img][rank] = make_float2((float)rr, (float)cc);
                g_pti[img][rank] = ((unsigned)rr << 16) | (unsigned)cc;
                rank++;
            }
            if (rank >= KP) break;
        }
    }
}

// ---------------- 4) Prim's MST: 128 thr x 8 nodes, scaled coords ----------------
// Coords scaled x32 and kept packed in smem (v<<5: no field carry). Then
// key = dx^2 + dy^2 + idx == 1024*d2 + idx exactly (same ordering / ties as the
// reference's float sqrt argmin). Real keys < 2^29. Retired nodes get px=46000:
// all future candidates land in [8.79e8, 2.39e9] -- above every real key, below
// 2^32, so they never win and the stale-key overwrite is harmless. A warp whose
// every lane has lmin >= 2^29 is fully retired (real keys only shrink) and can
// never own j, so it skips retire+update entirely.
__global__ void __launch_bounds__(T_MST) mst_kernel() {
    const int img = blockIdx.x;
    __shared__ unsigned s_xy[KP];
    __shared__ __align__(16) unsigned s_red[2][4];

    const int tid = threadIdx.x;
    const int lane = tid & 31;
    const int wrp = tid >> 5;

    for (int i = tid; i < KP; i += T_MST) s_xy[i] = g_pti[img][i] << 5;  // scaled packed
    __syncthreads();

    unsigned px[NPT], py[NPT], key[NPT];
    int src[NPT];
    const int base = tid * NPT;
    {
        const unsigned xy0 = s_xy[0];
        const unsigned jx = xy0 >> 16, jy = xy0 & 0xffffu;
#pragma unroll
        for (int q = 0; q < NPT; q++) {
            unsigned v = s_xy[base + q];
            px[q] = v >> 16; py[q] = v & 0xffffu;
            unsigned dx = px[q] - jx, dy = py[q] - jy;
            key[q] = dx * dx + dy * dy + (unsigned)(base + q);
            src[q] = 0;
        }
    }
    if (tid == 0) { key[0] = UMAXV; px[0] = SENTX; }

    unsigned lmin = UMAXV;
#pragma unroll
    for (int q = 0; q < NPT; q++) lmin = min(lmin, key[q]);
    unsigned wm = __reduce_min_sync(0xffffffffu, lmin);
    if (lane == 0) s_red[0][wrp] = wm;
    __syncthreads();
    uint4 A = *(const uint4*)&s_red[0][0];
    unsigned gm = min(min(A.x, A.y), min(A.z, A.w));
    int j = (int)(gm & 1023u);
    unsigned jxy = s_xy[j];                       // pipelined fetch

    int2* __restrict__ ep = g_edges[img];
#pragma unroll 1
    for (int step = 0; step < KP - 1; step++) {
        if (!__all_sync(0xffffffffu, lmin >= SKIPTHR)) {   // fully-retired warps skip all
            const int t = j - base;               // owner iff t in [0, NPT)
            // extract src[j&7] from PRE-update values via SEL tree
            int s01 = (t & 1) ? src[1] : src[0];
            int s23 = (t & 1) ? src[3] : src[2];
            int s45 = (t & 1) ? src[5] : src[4];
            int s67 = (t & 1) ? src[7] : src[6];
            int sA = (t & 2) ? s23 : s01;
            int sB = (t & 2) ? s67 : s45;
            int srcj = (t & 4) ? sB : sA;
            if ((unsigned)t < (unsigned)NPT)      // single guarded STG.64
                ep[step] = make_int2(srcj, j);

            const unsigned jx = jxy >> 16, jy = jxy & 0xffffu;
            lmin = UMAXV;
#pragma unroll
            for (int q = 0; q < NPT; q++) {
                bool own = (t == q);
                px[q]  = own ? SENTX : px[q];     // retire fused into update
                key[q] = own ? UMAXV : key[q];
                unsigned dx = px[q] - jx, dy = py[q] - jy;
                unsigned cand = dx * dx + dy * dy + (unsigned)(base + q);
                if (cand < key[q]) { key[q] = cand; src[q] = j; }   // strict <
                lmin = min(lmin, key[q]);
            }
        }
        wm = __reduce_min_sync(0xffffffffu, lmin);
        const int par = (step + 1) & 1;           // double buffer: 1 barrier/iter
        if (lane == 0) s_red[par][wrp] = wm;
        __syncthreads();
        A = *(const uint4*)&s_red[par][0];
        gm = min(min(A.x, A.y), min(A.z, A.w));
        j = (int)(gm & 1023u);
        jxy = s_xy[j];                            // prefetch for next iteration
    }
}

// ---------------- 5) per-sample loss + final, single block -----------------------
__device__ __forceinline__ float pdistf(float2 a, float2 b) {
    float dx = a.x - b.x, dy = a.y - b.y;
    return sqrtf(dx * dx + dy * dy);   // exact: integer d2 < 2^24
}

__global__ void __launch_bounds__(1024) loss_kernel(float* __restrict__ out) {
    __shared__ float sp[1024], sm[1024];
    __shared__ float part[8];
    const int tid = threadIdx.x;
    const int s = tid >> 7;        // 128 threads per sample
    const int g = tid & 127;

    const float2* __restrict__ Pp = g_pts[2 * s];
    const float2* __restrict__ Pm = g_pts[2 * s + 1];
    const int2*   __restrict__ Ep = g_edges[2 * s];
    const int2*   __restrict__ Em = g_edges[2 * s + 1];

    float accP = 0.0f, accM = 0.0f;
    for (int e = g; e < KP - 1; e += 128) {
        int2 e1 = Ep[e];
        float d1 = pdistf(Pp[e1.x], Pp[e1.y]) - pdistf(Pm[e1.x], Pm[e1.y]);
        accP += d1 * d1;
        int2 e2 = Em[e];
        float d2 = pdistf(Pp[e2.x], Pp[e2.y]) - pdistf(Pm[e2.x], Pm[e2.y]);
        accM += d2 * d2;
    }
    sp[tid] = accP; sm[tid] = accM;
    __syncthreads();
#pragma unroll
    for (int w = 64; w; w >>= 1) {
        if (g < w) { sp[tid] += sp[tid + w]; sm[tid] += sm[tid + w]; }
        __syncthreads();
    }
    if (g == 0) part[s] = sqrtf(sp[tid]) + sqrtf(sm[tid]);
    __syncthreads();
    if (tid == 0) {
        float t = 0.0f;
#pragma unroll
        for (int i = 0; i < NS; i++) t += part[i];
        out[0] = 0.1f * t / 8.0f;
    }
}

// ---------------- launch ----------------
extern "C" void kernel_launch(void* const* d_in, const int* in_sizes, int n_in,
                              void* d_out, int out_size) {
    const float* model_output = (const float*)d_in[1];
    const float* labels       = (const float*)d_in[2];
    float* out = (float*)d_out;

    binarize_kernel<<<(NS * HW) / 256, 256>>>(model_output, labels);
    lbp_bits_kernel<<<(NIMG * 8192) / 256, 256>>>();
    select_kernel<<<NIMG, 1024>>>();
    mst_kernel<<<NIMG, T_MST>>>();
    loss_kernel<<<1, 1024>>>(out);
}

// round 8
// speedup vs baseline: 1.3602x; 1.3602x over previous
#include <cuda_runtime.h>
#include <stdint.h>

#define HH 512
#define WW 512
#define HW (HH*WW)
#define NS 8            // samples
#define NIMG 16         // samples * {pred, mask}
#define KP 1024         // points per set
#define T_MST 256
#define NPT 4           // nodes per MST thread
#define UMAXV 0xFFFFFFFFu
#define SENTX 46000u    // retired-node x (scaled); cands land in [8.79e8, 2.39e9]
#define SKIPTHR 0x20000000u  // 2^29: all real keys below, all sentinel cands above
#define WPR 16          // 512/32 words per row

// ---------------- scratch (static device globals; no allocation) ----------------
__device__ unsigned g_mask[NIMG * 8192];          // binarized bitmasks (512x512 bits)
__device__ unsigned g_fbits[NIMG * 8192];         // lbp<THR flag bitmasks
__device__ float2   g_pts[NIMG][KP];              // selected points (r, c) float
__device__ unsigned g_pti[NIMG][KP];              // packed int coords (r<<16)|c
__device__ int2     g_edges[NIMG][KP - 1];        // MST edges (src, j)

// ---------------- 1) binarize -> bitmasks ---------------------------------------
__global__ void binarize_kernel(const float* __restrict__ mo, const float* __restrict__ lb) {
    int gid = blockIdx.x * blockDim.x + threadIdx.x;   // exactly NS*HW threads
    int s = gid >> 18;
    int p = gid & (HW - 1);
    unsigned bp = __ballot_sync(0xffffffffu, __ldg(mo + gid) > 0.0f);  // sigmoid>0.5 <=> x>0
    unsigned bm = __ballot_sync(0xffffffffu, __ldg(lb + gid) > 0.5f);
    if ((threadIdx.x & 31) == 0) {
        int w = p >> 5;
        g_mask[(2 * s)     * 8192 + w] = bp;
        g_mask[(2 * s + 1) * 8192 + w] = bm;
    }
}

// ---------------- 2) uniform LBP on bitmasks (exact) ----------------------------
__device__ __forceinline__ unsigned maj3(unsigned a, unsigned b, unsigned c) {
    return (a & b) | (c & (a ^ b));
}
__device__ __forceinline__ void sum8(const unsigned b[8],
                                     unsigned& s0, unsigned& s1, unsigned& s2, unsigned& s3) {
    unsigned t0 = b[0] ^ b[1], c0 = b[0] & b[1];
    unsigned t1 = b[2] ^ b[3], c1 = b[2] & b[3];
    unsigned t2 = b[4] ^ b[5], c2 = b[4] & b[5];
    unsigned t3 = b[6] ^ b[7], c3 = b[6] & b[7];
    unsigned u0 = t0 ^ t1, d0 = t0 & t1;
    unsigned u1 = t2 ^ t3, d1 = t2 & t3;
    s0 = u0 ^ u1;
    unsigned e0 = u0 & u1;
    unsigned p0 = c0 ^ c1 ^ c2, q0 = maj3(c0, c1, c2);
    unsigned p1 = c3 ^ d0 ^ d1, q1 = maj3(c3, d0, d1);
    s1 = p0 ^ p1 ^ e0;
    unsigned q2 = maj3(p0, p1, e0);
    s2 = q0 ^ q1 ^ q2;
    s3 = maj3(q0, q1, q2);
}

struct RowBits { unsigned C, Lc, Rc, QL, QR; };

__device__ __forceinline__ RowBits rowbits(const unsigned* __restrict__ M, int y, int w) {
    RowBits rb;
    unsigned c = __ldg(M + y * WPR + w);
    unsigned prev = (w > 0)   ? __ldg(M + y * WPR + w - 1) : 0u;
    unsigned next = (w < 15)  ? __ldg(M + y * WPR + w + 1) : 0u;
    unsigned Lc = (w > 0)  ? __funnelshift_l(prev, c, 1) : ((c << 1) | (c & 1u));
    unsigned Rc = (w < 15) ? __funnelshift_r(c, next, 1) : ((c >> 1) | (c & 0x80000000u));
    unsigned QL = Lc & c;
    if (w == 0) QL = (QL & ~1u) | (c & Rc & 1u);   // col0: quad cols {0,1}
    rb.C = c; rb.Lc = Lc; rb.Rc = Rc; rb.QL = QL; rb.QR = c & Rc;
    return rb;
}

__global__ void lbp_bits_kernel() {
    int gid = blockIdx.x * blockDim.x + threadIdx.x;   // NIMG*8192 threads
    int img = gid >> 13;
    int rem = gid & 8191;
    int r = rem >> 4;
    int w = rem & 15;
    const unsigned* __restrict__ M = g_mask + img * 8192;

    int rm = max(r - 1, 0);
    int rp = min(r + 1, HH - 1);
    RowBits Rr  = rowbits(M, r,  w);
    RowBits Rrp = rowbits(M, rp, w);
    RowBits Rpm0, Rpm1;         // row pair for dr = -0.707: {clamp(r-1), clamp(r-1)+1}
    if (r == 0) { Rpm0 = Rr; Rpm1 = Rrp; }
    else        { Rpm0 = rowbits(M, rm, w); Rpm1 = Rr; }
    unsigned Crm = (r == 0) ? Rr.C : Rpm0.C;   // C(clamp(r-1))

    unsigned b[8];
    b[0] = Rr.Rc;                 // (0, +1)
    b[2] = Crm;                   // (-1, 0)
    b[4] = Rr.Lc;                 // (0, -1)
    b[6] = Rrp.C;                 // (+1, 0)
    b[1] = Rpm0.QR & Rpm1.QR;     // (-.707, +.707)
    b[3] = Rpm0.QL & Rpm1.QL;     // (-.707, -.707)
    b[5] = Rr.QL & Rrp.QL;        // (+.707, -.707)
    b[7] = Rr.QR & Rrp.QR;        // (+.707, +.707)

    unsigned s0, s1, s2, s3;
    sum8(b, s0, s1, s2, s3);
    unsigned ok_s = ~(s3 | (s2 & (s1 | s0)));     // sum < 5

    unsigned ch[8];
#pragma unroll
    for (int k = 0; k < 8; k++) ch[k] = b[k] ^ b[(k + 7) & 7];
    unsigned c0, c1, c2, c3;
    sum8(ch, c0, c1, c2, c3);
    unsigned ok_ch = ~(c2 | c3);                  // changes <= 2 (changes is even)

    g_fbits[gid] = Rr.C & ok_s & ok_ch;           // center must be 1
}

// ---------------- 3) ordered compaction from flag bitmask ------------------------
__global__ void __launch_bounds__(1024) select_kernel() {
    const int img = blockIdx.x;
    __shared__ int s_wtot[32];
    __shared__ int s_woff[32];
    const int tid = threadIdx.x, lane = tid & 31, wrp = tid >> 5;

    g_pts[img][tid] = make_float2(0.0f, 0.0f);    // zero-pad
    g_pti[img][tid] = 0u;

    const unsigned* __restrict__ F = g_fbits + img * 8192;
    unsigned wv[8];
    int cnt = 0;
    const int w0 = tid * 8;
#pragma unroll
    for (int i = 0; i < 8; i++) { wv[i] = __ldg(F + w0 + i); cnt += __popc(wv[i]); }

    // block-wide exclusive prefix
    int incl = cnt;
#pragma unroll
    for (int d = 1; d < 32; d <<= 1) {
        int n = __shfl_up_sync(0xffffffffu, incl, d);
        if (lane >= d) incl += n;
    }
    if (lane == 31) s_wtot[wrp] = incl;
    __syncthreads();
    if (wrp == 0) {
        int t = s_wtot[lane];
        int ti = t;
#pragma unroll
        for (int d = 1; d < 32; d <<= 1) {
            int n = __shfl_up_sync(0xffffffffu, ti, d);
            if (lane >= d) ti += n;
        }
        s_woff[lane] = ti - t;
    }
    __syncthreads();
    int rank = s_woff[wrp] + (incl - cnt);

    if (rank < KP && cnt > 0) {
#pragma unroll
        for (int i = 0; i < 8; i++) {
            unsigned m = wv[i];
            int pbase = (w0 + i) << 5;
            while (m && rank < KP) {
                int b = __ffs(m) - 1;
                m &= m - 1;
                int pp = pbase + b;
                int rr = pp >> 9, cc = pp & 511;
                g_pts[img][rank] = make_float2((float)rr, (float)cc);
                g_pti[img][rank] = ((unsigned)rr << 16) | (unsigned)cc;
                rank++;
            }
            if (rank >= KP) break;
        }
    }
}

// ---------------- 4) Prim's MST: 256 thr x 4 nodes, scaled coords ----------------
// Coords scaled x32, packed in smem (v<<5: no field carry). key = dx^2+dy^2+idx
// == 1024*d2 + idx exactly: same ordering and ties as the reference float-sqrt
// argmin. Real keys < 2^29. Retired nodes: px=SENTX => future candidates in
// [8.79e8, 2.39e9] -- above all real keys, below 2^32; stale overwrites are
// harmless. Warp with all lmin >= 2^29 is fully retired, can never own j, and
// skips retire+emit+update entirely. 256 threads = 2 warps/SMSP so the
// redux->STS->BAR->LDS chain is latency-hidden (128-thread variant regressed).
__global__ void __launch_bounds__(T_MST) mst_kernel() {
    const int img = blockIdx.x;
    __shared__ unsigned s_xy[KP];
    __shared__ __align__(16) unsigned s_red[2][8];

    const int tid = threadIdx.x;
    const int lane = tid & 31;
    const int wrp = tid >> 5;

    for (int i = tid; i < KP; i += T_MST) s_xy[i] = g_pti[img][i] << 5;  // scaled packed
    __syncthreads();

    unsigned px[NPT], py[NPT], key[NPT];
    int src[NPT];
    const int base = tid * NPT;
    {
        const unsigned xy0 = s_xy[0];
        const unsigned jx = xy0 >> 16, jy = xy0 & 0xffffu;
#pragma unroll
        for (int q = 0; q < NPT; q++) {
            unsigned v = s_xy[base + q];
            px[q] = v >> 16; py[q] = v & 0xffffu;
            unsigned dx = px[q] - jx, dy = py[q] - jy;
            key[q] = dx * dx + dy * dy + (unsigned)(base + q);
            src[q] = 0;
        }
    }
    if (tid == 0) { key[0] = UMAXV; px[0] = SENTX; }

    unsigned lmin = UMAXV;
#pragma unroll
    for (int q = 0; q < NPT; q++) lmin = min(lmin, key[q]);
    unsigned wm = __reduce_min_sync(0xffffffffu, lmin);
    if (lane == 0) s_red[0][wrp] = wm;
    __syncthreads();
    uint4 A = *(const uint4*)&s_red[0][0];
    uint4 B = *(const uint4*)&s_red[0][4];
    unsigned gm = min(min(min(A.x, A.y), min(A.z, A.w)),
                      min(min(B.x, B.y), min(B.z, B.w)));
    int j = (int)(gm & 1023u);
    unsigned jxy = s_xy[j];                       // pipelined fetch

    int2* __restrict__ ep = g_edges[img];
#pragma unroll 1
    for (int step = 0; step < KP - 1; step++) {
        if (!__all_sync(0xffffffffu, lmin >= SKIPTHR)) {   // fully-retired warps skip all
            const int t = j - base;               // owner iff t in [0, NPT)
            // extract src[j&3] from PRE-update values via SEL tree
            int sA = (t == 1) ? src[1] : src[0];
            int sB = (t == 3) ? src[3] : src[2];
            int srcj = (t >= 2) ? sB : sA;
            if ((unsigned)t < (unsigned)NPT)      // single guarded STG.64
                ep[step] = make_int2(srcj, j);

            const unsigned jx = jxy >> 16, jy = jxy & 0xffffu;
            lmin = UMAXV;
#pragma unroll
            for (int q = 0; q < NPT; q++) {
                bool own = (t == q);
                px[q]  = own ? SENTX : px[q];     // retire fused into update
                key[q] = own ? UMAXV : key[q];
                unsigned dx = px[q] - jx, dy = py[q] - jy;
                unsigned cand = dx * dx + dy * dy + (unsigned)(base + q);
                if (cand < key[q]) { key[q] = cand; src[q] = j; }   // strict <
                lmin = min(lmin, key[q]);
            }
        }
        wm = __reduce_min_sync(0xffffffffu, lmin);
        const int par = (step + 1) & 1;           // double buffer: 1 barrier/iter
        if (lane == 0) s_red[par][wrp] = wm;
        __syncthreads();
        A = *(const uint4*)&s_red[par][0];
        B = *(const uint4*)&s_red[par][4];
        gm = min(min(min(A.x, A.y), min(A.z, A.w)),
                 min(min(B.x, B.y), min(B.z, B.w)));
        j = (int)(gm & 1023u);
        jxy = s_xy[j];                            // prefetch for next iteration
    }
}

// ---------------- 5) per-sample loss + final, single block -----------------------
__device__ __forceinline__ float pdistf(float2 a, float2 b) {
    float dx = a.x - b.x, dy = a.y - b.y;
    return sqrtf(dx * dx + dy * dy);   // exact: integer d2 < 2^24
}

__global__ void __launch_bounds__(1024) loss_kernel(float* __restrict__ out) {
    __shared__ float sp[1024], sm[1024];
    __shared__ float part[8];
    const int tid = threadIdx.x;
    const int s = tid >> 7;        // 128 threads per sample
    const int g = tid & 127;

    const float2* __restrict__ Pp = g_pts[2 * s];
    const float2* __restrict__ Pm = g_pts[2 * s + 1];
    const int2*   __restrict__ Ep = g_edges[2 * s];
    const int2*   __restrict__ Em = g_edges[2 * s + 1];

    float accP = 0.0f, accM = 0.0f;
    for (int e = g; e < KP - 1; e += 128) {
        int2 e1 = Ep[e];
        float d1 = pdistf(Pp[e1.x], Pp[e1.y]) - pdistf(Pm[e1.x], Pm[e1.y]);
        accP += d1 * d1;
        int2 e2 = Em[e];
        float d2 = pdistf(Pp[e2.x], Pp[e2.y]) - pdistf(Pm[e2.x], Pm[e2.y]);
        accM += d2 * d2;
    }
    sp[tid] = accP; sm[tid] = accM;
    __syncthreads();
#pragma unroll
    for (int w = 64; w; w >>= 1) {
        if (g < w) { sp[tid] += sp[tid + w]; sm[tid] += sm[tid + w]; }
        __syncthreads();
    }
    if (g == 0) part[s] = sqrtf(sp[tid]) + sqrtf(sm[tid]);
    __syncthreads();
    if (tid == 0) {
        float t = 0.0f;
#pragma unroll
        for (int i = 0; i < NS; i++) t += part[i];
        out[0] = 0.1f * t / 8.0f;
    }
}

// ---------------- launch ----------------
extern "C" void kernel_launch(void* const* d_in, const int* in_sizes, int n_in,
                              void* d_out, int out_size) {
    const float* model_output = (const float*)d_in[1];
    const float* labels       = (const float*)d_in[2];
    float* out = (float*)d_out;

    binarize_kernel<<<(NS * HW) / 256, 256>>>(model_output, labels);
    lbp_bits_kernel<<<(NIMG * 8192) / 256, 256>>>();
    select_kernel<<<NIMG, 1024>>>();
    mst_kernel<<<NIMG, T_MST>>>();
    loss_kernel<<<1, 1024>>>(out);
}

// round 9
// speedup vs baseline: 1.4959x; 1.0997x over previous
#include <cuda_runtime.h>
#include <stdint.h>

#define HH 512
#define WW 512
#define HW (HH*WW)
#define NS 8            // samples
#define NIMG 16         // samples * {pred, mask}
#define KP 1024         // points per set
#define T_MST 256
#define NPT 4           // nodes per MST thread
#define UMAXV 0xFFFFFFFFu
#define SENTX 46000u    // retired-node x (scaled); cands land in [8.79e8, 2.39e9]
#define SKIPTHR 0x20000000u  // 2^29: real keys <= 5.348e8 < 2^29; sentinel cands above
#define WPR 16          // 512/32 words per row

// ---------------- scratch (static device globals; no allocation) ----------------
__device__ unsigned g_mask[NIMG * 8192];          // binarized bitmasks (512x512 bits)
__device__ unsigned g_fbits[NIMG * 8192];         // lbp<THR flag bitmasks
__device__ float2   g_pts[NIMG][KP];              // selected points (r, c) float
__device__ unsigned g_pti[NIMG][KP];              // packed int coords (r<<16)|c
__device__ int2     g_edges[NIMG][KP - 1];        // MST edges (src, j)
__device__ float    g_part[NIMG];                 // per-(sample,tree) partial norms

// ---------------- 1) binarize -> bitmasks ---------------------------------------
__global__ void binarize_kernel(const float* __restrict__ mo, const float* __restrict__ lb) {
    int gid = blockIdx.x * blockDim.x + threadIdx.x;   // exactly NS*HW threads
    int s = gid >> 18;
    int p = gid & (HW - 1);
    unsigned bp = __ballot_sync(0xffffffffu, __ldg(mo + gid) > 0.0f);  // sigmoid>0.5 <=> x>0
    unsigned bm = __ballot_sync(0xffffffffu, __ldg(lb + gid) > 0.5f);
    if ((threadIdx.x & 31) == 0) {
        int w = p >> 5;
        g_mask[(2 * s)     * 8192 + w] = bp;
        g_mask[(2 * s + 1) * 8192 + w] = bm;
    }
}

// ---------------- 2) uniform LBP on bitmasks (exact) ----------------------------
__device__ __forceinline__ unsigned maj3(unsigned a, unsigned b, unsigned c) {
    return (a & b) | (c & (a ^ b));
}
__device__ __forceinline__ void sum8(const unsigned b[8],
                                     unsigned& s0, unsigned& s1, unsigned& s2, unsigned& s3) {
    unsigned t0 = b[0] ^ b[1], c0 = b[0] & b[1];
    unsigned t1 = b[2] ^ b[3], c1 = b[2] & b[3];
    unsigned t2 = b[4] ^ b[5], c2 = b[4] & b[5];
    unsigned t3 = b[6] ^ b[7], c3 = b[6] & b[7];
    unsigned u0 = t0 ^ t1, d0 = t0 & t1;
    unsigned u1 = t2 ^ t3, d1 = t2 & t3;
    s0 = u0 ^ u1;
    unsigned e0 = u0 & u1;
    unsigned p0 = c0 ^ c1 ^ c2, q0 = maj3(c0, c1, c2);
    unsigned p1 = c3 ^ d0 ^ d1, q1 = maj3(c3, d0, d1);
    s1 = p0 ^ p1 ^ e0;
    unsigned q2 = maj3(p0, p1, e0);
    s2 = q0 ^ q1 ^ q2;
    s3 = maj3(q0, q1, q2);
}

struct RowBits { unsigned C, Lc, Rc, QL, QR; };

__device__ __forceinline__ RowBits rowbits(const unsigned* __restrict__ M, int y, int w) {
    RowBits rb;
    unsigned c = __ldg(M + y * WPR + w);
    unsigned prev = (w > 0)   ? __ldg(M + y * WPR + w - 1) : 0u;
    unsigned next = (w < 15)  ? __ldg(M + y * WPR + w + 1) : 0u;
    unsigned Lc = (w > 0)  ? __funnelshift_l(prev, c, 1) : ((c << 1) | (c & 1u));
    unsigned Rc = (w < 15) ? __funnelshift_r(c, next, 1) : ((c >> 1) | (c & 0x80000000u));
    unsigned QL = Lc & c;
    if (w == 0) QL = (QL & ~1u) | (c & Rc & 1u);   // col0: quad cols {0,1}
    rb.C = c; rb.Lc = Lc; rb.Rc = Rc; rb.QL = QL; rb.QR = c & Rc;
    return rb;
}

__global__ void lbp_bits_kernel() {
    int gid = blockIdx.x * blockDim.x + threadIdx.x;   // NIMG*8192 threads
    int img = gid >> 13;
    int rem = gid & 8191;
    int r = rem >> 4;
    int w = rem & 15;
    const unsigned* __restrict__ M = g_mask + img * 8192;

    int rm = max(r - 1, 0);
    int rp = min(r + 1, HH - 1);
    RowBits Rr  = rowbits(M, r,  w);
    RowBits Rrp = rowbits(M, rp, w);
    RowBits Rpm0, Rpm1;         // row pair for dr = -0.707: {clamp(r-1), clamp(r-1)+1}
    if (r == 0) { Rpm0 = Rr; Rpm1 = Rrp; }
    else        { Rpm0 = rowbits(M, rm, w); Rpm1 = Rr; }
    unsigned Crm = (r == 0) ? Rr.C : Rpm0.C;   // C(clamp(r-1))

    unsigned b[8];
    b[0] = Rr.Rc;                 // (0, +1)
    b[2] = Crm;                   // (-1, 0)
    b[4] = Rr.Lc;                 // (0, -1)
    b[6] = Rrp.C;                 // (+1, 0)
    b[1] = Rpm0.QR & Rpm1.QR;     // (-.707, +.707)
    b[3] = Rpm0.QL & Rpm1.QL;     // (-.707, -.707)
    b[5] = Rr.QL & Rrp.QL;        // (+.707, -.707)
    b[7] = Rr.QR & Rrp.QR;        // (+.707, +.707)

    unsigned s0, s1, s2, s3;
    sum8(b, s0, s1, s2, s3);
    unsigned ok_s = ~(s3 | (s2 & (s1 | s0)));     // sum < 5

    unsigned ch[8];
#pragma unroll
    for (int k = 0; k < 8; k++) ch[k] = b[k] ^ b[(k + 7) & 7];
    unsigned c0, c1, c2, c3;
    sum8(ch, c0, c1, c2, c3);
    unsigned ok_ch = ~(c2 | c3);                  // changes <= 2 (changes is even)

    g_fbits[gid] = Rr.C & ok_s & ok_ch;           // center must be 1
}

// ---------------- 3) ordered compaction from flag bitmask ------------------------
__global__ void __launch_bounds__(1024) select_kernel() {
    const int img = blockIdx.x;
    __shared__ int s_wtot[32];
    __shared__ int s_woff[32];
    const int tid = threadIdx.x, lane = tid & 31, wrp = tid >> 5;

    g_pts[img][tid] = make_float2(0.0f, 0.0f);    // zero-pad
    g_pti[img][tid] = 0u;

    const unsigned* __restrict__ F = g_fbits + img * 8192;
    unsigned wv[8];
    int cnt = 0;
    const int w0 = tid * 8;
#pragma unroll
    for (int i = 0; i < 8; i++) { wv[i] = __ldg(F + w0 + i); cnt += __popc(wv[i]); }

    // block-wide exclusive prefix
    int incl = cnt;
#pragma unroll
    for (int d = 1; d < 32; d <<= 1) {
        int n = __shfl_up_sync(0xffffffffu, incl, d);
        if (lane >= d) incl += n;
    }
    if (lane == 31) s_wtot[wrp] = incl;
    __syncthreads();
    if (wrp == 0) {
        int t = s_wtot[lane];
        int ti = t;
#pragma unroll
        for (int d = 1; d < 32; d <<= 1) {
            int n = __shfl_up_sync(0xffffffffu, ti, d);
            if (lane >= d) ti += n;
        }
        s_woff[lane] = ti - t;
    }
    __syncthreads();
    int rank = s_woff[wrp] + (incl - cnt);

    if (rank < KP && cnt > 0) {
#pragma unroll
        for (int i = 0; i < 8; i++) {
            unsigned m = wv[i];
            int pbase = (w0 + i) << 5;
            while (m && rank < KP) {
                int b = __ffs(m) - 1;
                m &= m - 1;
                int pp = pbase + b;
                int rr = pp >> 9, cc = pp & 511;
                g_pts[img][rank] = make_float2((float)rr, (float)cc);
                g_pti[img][rank] = ((unsigned)rr << 16) | (unsigned)cc;
                rank++;
            }
            if (rank >= KP) break;
        }
    }
}

// ---------------- 4) Prim's MST: 256 thr x 4 nodes, merged retire ----------------
// Coords scaled x32, packed in smem (v<<5: no field carry). key = dx^2+dy^2+idx
// == 1024*d2 + idx exactly: same ordering and ties as the reference float-sqrt
// argmin. Real keys <= 5.348e8 < 2^29. Retirement is MERGED into the update:
// the owner sets px=SENTX and forces key = cand (sentinel-distance, in
// [8.79e8, 2.39e9] -- above every real key, below 2^32), so retired nodes can
// never win the argmin. Warp with all lmin >= 2^29 is fully retired, can never
// own j, and skips everything. 256 threads = 2 warps/SMSP hides the
// redux->STS->BAR->LDS chain (128-thread variant regressed).
__global__ void __launch_bounds__(T_MST) mst_kernel() {
    const int img = blockIdx.x;
    __shared__ unsigned s_xy[KP];
    __shared__ __align__(16) unsigned s_red[2][8];

    const int tid = threadIdx.x;
    const int lane = tid & 31;
    const int wrp = tid >> 5;

    for (int i = tid; i < KP; i += T_MST) s_xy[i] = g_pti[img][i] << 5;  // scaled packed
    __syncthreads();

    unsigned px[NPT], py[NPT], key[NPT];
    int src[NPT];
    const int base = tid * NPT;
    {
        const unsigned xy0 = s_xy[0];
        const unsigned jx = xy0 >> 16, jy = xy0 & 0xffffu;
#pragma unroll
        for (int q = 0; q < NPT; q++) {
            unsigned v = s_xy[base + q];
            px[q] = v >> 16; py[q] = v & 0xffffu;
            unsigned dx = px[q] - jx, dy = py[q] - jy;
            key[q] = dx * dx + dy * dy + (unsigned)(base + q);
            src[q] = 0;
        }
    }
    if (tid == 0) { key[0] = UMAXV; px[0] = SENTX; }

    unsigned lmin = UMAXV;
#pragma unroll
    for (int q = 0; q < NPT; q++) lmin = min(lmin, key[q]);
    unsigned wm = __reduce_min_sync(0xffffffffu, lmin);
    if (lane == 0) s_red[0][wrp] = wm;
    __syncthreads();
    uint4 A = *(const uint4*)&s_red[0][0];
    uint4 B = *(const uint4*)&s_red[0][4];
    unsigned gm = min(min(min(A.x, A.y), min(A.z, A.w)),
                      min(min(B.x, B.y), min(B.z, B.w)));
    int j = (int)(gm & 1023u);
    unsigned jxy = s_xy[j];                       // pipelined fetch

    int2* __restrict__ ep = g_edges[img];
#pragma unroll 1
    for (int step = 0; step < KP - 1; step++) {
        if (!__all_sync(0xffffffffu, lmin >= SKIPTHR)) {   // fully-retired warps skip all
            const int t = j - base;               // owner iff t in [0, NPT)
            // extract src[j&3] from PRE-update values via SEL tree
            int sA = (t == 1) ? src[1] : src[0];
            int sB = (t == 3) ? src[3] : src[2];
            int srcj = (t >= 2) ? sB : sA;
            if ((unsigned)t < (unsigned)NPT)      // single guarded STG.64
                ep[step] = make_int2(srcj, j);

            const unsigned jx = jxy >> 16, jy = jxy & 0xffffu;
            lmin = UMAXV;
#pragma unroll
            for (int q = 0; q < NPT; q++) {
                bool own = (t == q);
                px[q] = own ? SENTX : px[q];      // sentinel coordinate
                unsigned dx = px[q] - jx, dy = py[q] - jy;
                unsigned cand = dx * dx + dy * dy + (unsigned)(base + q);
                // merged retire: owner unconditionally takes cand (>= SKIPTHR)
                bool upd = own | (cand < key[q]); // strict <, keeps old src on tie
                key[q] = upd ? cand : key[q];
                src[q] = upd ? j : src[q];
                lmin = min(lmin, key[q]);
            }
        }
        wm = __reduce_min_sync(0xffffffffu, lmin);
        const int par = (step + 1) & 1;           // double buffer: 1 barrier/iter
        if (lane == 0) s_red[par][wrp] = wm;
        __syncthreads();
        A = *(const uint4*)&s_red[par][0];
        B = *(const uint4*)&s_red[par][4];
        gm = min(min(min(A.x, A.y), min(A.z, A.w)),
                 min(min(B.x, B.y), min(B.z, B.w)));
        j = (int)(gm & 1023u);
        jxy = s_xy[j];                            // prefetch for next iteration
    }
}

// ---------------- 5) per-(sample,tree) loss: grid=16 -----------------------------
__device__ __forceinline__ float pdistf(float2 a, float2 b) {
    float dx = a.x - b.x, dy = a.y - b.y;
    return sqrtf(dx * dx + dy * dy);   // exact: integer d2 < 2^24
}

__global__ void __launch_bounds__(256) loss_kernel() {
    const int blk = blockIdx.x;        // 16 blocks: (sample s, tree t)
    const int s = blk >> 1;
    const int t = blk & 1;             // 0: pred-tree edges, 1: mask-tree edges

    const float2* __restrict__ Pp = g_pts[2 * s];
    const float2* __restrict__ Pm = g_pts[2 * s + 1];
    const int2*   __restrict__ E  = g_edges[2 * s + t];

    float acc = 0.0f;
    for (int e = threadIdx.x; e < KP - 1; e += 256) {
        int2 ee = E[e];
        float d = pdistf(Pp[ee.x], Pp[ee.y]) - pdistf(Pm[ee.x], Pm[ee.y]);
        acc += d * d;
    }
    __shared__ float red[256];
    const int tid = threadIdx.x;
    red[tid] = acc;
    __syncthreads();
#pragma unroll
    for (int w = 128; w; w >>= 1) {
        if (tid < w) red[tid] += red[tid + w];
        __syncthreads();
    }
    if (tid == 0) g_part[blk] = sqrtf(red[0]);
}

__global__ void final_kernel(float* __restrict__ out) {
    float t = 0.0f;
#pragma unroll
    for (int i = 0; i < NIMG; i++) t += g_part[i];
    out[0] = 0.1f * t / 8.0f;
}

// ---------------- launch ----------------
extern "C" void kernel_launch(void* const* d_in, const int* in_sizes, int n_in,
                              void* d_out, int out_size) {
    const float* model_output = (const float*)d_in[1];
    const float* labels       = (const float*)d_in[2];
    float* out = (float*)d_out;

    binarize_kernel<<<(NS * HW) / 256, 256>>>(model_output, labels);
    lbp_bits_kernel<<<(NIMG * 8192) / 256, 256>>>();
    select_kernel<<<NIMG, 1024>>>();
    mst_kernel<<<NIMG, T_MST>>>();
    loss_kernel<<<NIMG, 256>>>();
    final_kernel<<<1, 1>>>(out);
}